// round 10
// baseline (speedup 1.0000x reference)
#include <cuda_runtime.h>
#include <cstdint>

// ---------------------------------------------------------------------------
// LocationSensitiveAttention — barrier-free multi-kernel CUDA-graph design.
// B=32, T_ENC=1024, T_DEC=512, E=U=512, FILTERS=32, KERNEL=31.
//
// 514 launches per call:
//   k_weff                : fold conv_w @ w_loc -> Weff[31,512] (f32x2 packed)
//   kA(t), t=0..511       : finalize step t-1 (e, prev) + compute step t
//                           (loc Toeplitz GEMM + tanh + v_a reduce + exp)
//   kE                    : finalize e(511)
//   kC                    : c = e_out @ enc  (batched GEMM, overwrites c)
// Cross-step/cross-CTA ordering comes from kernel-launch edges. State
// (prev, exs, psum) is double-buffered so a launch never reads a location
// another CTA writes in the same launch.
//
// R9: dropped all hand-written cache-hint PTX (two container failures on the
// createpolicy/cache_hint variant). Structural latency fix instead:
// 256 CTAs x 256 threads (8 slices of 128 te per batch) -> ~31K regs/CTA ->
// 2 CTAs co-resident per SM, single wave over all 148 SMs. The sibling CTA
// hides DRAM latency and barrier phases that held issue to 57.5% in R6.
// e_out written with __stcs (streaming) to reduce L2 churn against enc.
// ---------------------------------------------------------------------------

#define BQ 32
#define TENC 1024
#define TDEC 512
#define EDIM 512
#define NFILT 32
#define KW 31
#define NUP 256              // u-pairs (EDIM/2)
#define SLICES 8             // te-slices per batch
#define TE_SL 128            // te per slice

typedef unsigned long long ull;

// static device scratch (no allocation)
__device__ ull   g_W2[KW * NUP];          // Weff packed f32x2 [k][upair]
__device__ ull   g_cb2[NUP];              // conv_b @ w_loc packed
__device__ float g_prevb[2][BQ * TENC];   // double-buffered cumulative align
__device__ float g_exs[2][BQ * TENC];     // double-buffered exp(e_raw)
__device__ float g_psum[2][BQ * SLICES];  // double-buffered per-slice sums

// ---- f32x2 helpers --------------------------------------------------------
__device__ __forceinline__ ull fma2(ull a, ull b, ull c) {
    ull d;
    asm("fma.rn.f32x2 %0, %1, %2, %3;" : "=l"(d) : "l"(a), "l"(b), "l"(c));
    return d;
}
__device__ __forceinline__ ull add2(ull a, ull b) {
    ull d;
    asm("add.rn.f32x2 %0, %1, %2;" : "=l"(d) : "l"(a), "l"(b));
    return d;
}
__device__ __forceinline__ ull pack2(float lo, float hi) {
    ull d;
    asm("mov.b64 %0, {%1, %2};" : "=l"(d) : "f"(lo), "f"(hi));
    return d;
}
__device__ __forceinline__ void unpack2(ull v, float& lo, float& hi) {
    asm("mov.b64 {%0, %1}, %2;" : "=f"(lo), "=f"(hi) : "l"(v));
}
// tanh(x) = 1 - 2/(1+exp(2x)); ex2+rcp approx (~1e-6), saturates correctly.
__device__ __forceinline__ float fast_tanh(float x) {
    float m = x * 2.8853900817779268f;    // 2*log2(e)
    float t, r;
    asm("ex2.approx.f32 %0, %1;" : "=f"(t) : "f"(m));
    float d = 1.0f + t;
    asm("rcp.approx.f32 %0, %1;" : "=f"(r) : "f"(d));
    return fmaf(-2.0f, r, 1.0f);
}

// ---- weight folding -------------------------------------------------------
__global__ void k_weff(const float* __restrict__ cw, const float* __restrict__ cb,
                       const float* __restrict__ wl) {
    int idx = blockIdx.x * blockDim.x + threadIdx.x;
    if (idx < KW * NUP) {
        int k = idx / NUP, up = idx % NUP;
        float slo = 0.0f, shi = 0.0f;
        #pragma unroll
        for (int f = 0; f < NFILT; ++f) {
            float w = cw[k * NFILT + f];
            slo += w * wl[f * EDIM + 2 * up];
            shi += w * wl[f * EDIM + 2 * up + 1];
        }
        g_W2[idx] = pack2(slo, shi);
    }
    if (idx < NUP) {
        float slo = 0.0f, shi = 0.0f;
        #pragma unroll
        for (int f = 0; f < NFILT; ++f) {
            float w = cb[f];
            slo += w * wl[f * EDIM + 2 * idx];
            shi += w * wl[f * EDIM + 2 * idx + 1];
        }
        g_cb2[idx] = pack2(slo, shi);
    }
}

// ---- per-step kernel ------------------------------------------------------
// CTA (b, slice): b = bx>>3, slice = bx&7; owns te in [slice*128, slice*128+128).
// 8 warps; warp w covers upairs w*32..w*32+31 over all 128 te of the slice.
// Buffers: kA(t) reads prevb[t&1] (= prev(t-2)) and exs/psum[(t+1)&1] (= step
// t-1); writes prevb[(t+1)&1] (= prev(t-1)) and exs/psum[t&1] (= step t).
__global__ void __launch_bounds__(256)
kA(int t, const float* __restrict__ enc, const float* __restrict__ dec,
   const float* __restrict__ va, const float* __restrict__ ba,
   float* __restrict__ out) {
    const int bx = blockIdx.x;
    const int b = bx >> 3;
    const int slice = bx & 7;
    const int te0 = slice * TE_SL;

    const int tid = threadIdx.x;
    const int lane = tid & 31;
    const int wu = tid >> 5;            // warp index == u-group (0..7)
    const int upair = wu * 32 + lane;   // 0..255

    __shared__ ull p2s[TE_SL + KW + 1];       // dup-packed prev(t-1) window
    __shared__ float part_s[8][TE_SL];
    __shared__ float red_s[8];

    const ull* enc2 = reinterpret_cast<const ull*>(enc);
    const ull* dec2 = reinterpret_cast<const ull*>(dec);
    const ull* va2  = reinterpret_cast<const ull*>(va);
    const ull* ba2  = reinterpret_cast<const ull*>(ba);
    float* e_out = out + (size_t)BQ * TDEC * EDIM;

    const int rdE = (t + 1) & 1;        // exs/psum buffer of step t-1
    const int wrE = t & 1;

    float inv = 0.0f;
    if (t > 0) {
        const float* ps = &g_psum[rdE][b * SLICES];
        float s = 0.0f;
        #pragma unroll
        for (int i = 0; i < SLICES; ++i) s += ps[i];
        inv = 1.0f / s;
    }

    // finalize step t-1 (e, prev) + stage conv window (158 values)
    if (tid < TE_SL + KW - 1) {
        int te_g = te0 - 15 + tid;
        float pv = 0.0f, e = 0.0f;
        if (te_g >= 0 && te_g < TENC && t > 0) {
            pv = g_prevb[t & 1][b * TENC + te_g];
            e = g_exs[rdE][b * TENC + te_g] * inv;
            pv += e;
        }
        p2s[tid] = pack2(pv, pv);
        if (tid >= 15 && tid < 15 + TE_SL) {   // own te range
            g_prevb[(t + 1) & 1][b * TENC + te_g] = pv;
            if (t > 0)
                __stcs(&e_out[((size_t)b * TDEC + (t - 1)) * TENC + te_g], e);
        }
    }

    float va_lo, va_hi;
    unpack2(__ldg(va2 + upair), va_lo, va_hi);
    ull qb2 = add2(add2(__ldg(dec2 + ((size_t)b * TDEC + t) * NUP + upair),
                        __ldg(ba2 + upair)),
                   g_cb2[upair]);
    const ull* enc_row = enc2 + ((size_t)b * TENC + te0) * NUP + upair;
    __syncthreads();

    // loc (Toeplitz, f32x2) + tanh + v_a reduce — 16 tiles of 8 te
    #pragma unroll 1
    for (int tile = 0; tile < 16; ++tile) {
        const int te_l = tile * 8;

        // hoist enc loads above the FFMA2 chain: their latency is covered by
        // the 31x8 dependence-free FMA stream below
        ull ev[8];
        #pragma unroll
        for (int j = 0; j < 8; ++j)
            ev[j] = __ldg(enc_row + (size_t)(te_l + j) * NUP);

        ull r[8], acc[8];
        #pragma unroll
        for (int j = 0; j < 8; ++j) { r[j] = p2s[te_l + j]; acc[j] = 0ull; }
        #pragma unroll
        for (int k = 0; k < KW; ++k) {
            ull wk = __ldg(&g_W2[k * NUP + upair]);
            #pragma unroll
            for (int j = 0; j < 8; ++j)
                acc[j] = fma2(r[(k + j) & 7], wk, acc[j]);
            if (k < KW - 1) r[k & 7] = p2s[te_l + k + 8];
        }

        float pj[8];
        #pragma unroll
        for (int j = 0; j < 8; ++j) {
            ull arg = add2(add2(acc[j], ev[j]), qb2);
            float xlo, xhi;
            unpack2(arg, xlo, xhi);
            pj[j] = fmaf(va_hi, fast_tanh(xhi), va_lo * fast_tanh(xlo));
        }
        #pragma unroll
        for (int j = 0; j < 8; ++j) {
            #pragma unroll
            for (int m = 16; m >= 1; m >>= 1)
                pj[j] += __shfl_xor_sync(0xffffffffu, pj[j], m);
        }
        if (lane == 0) {
            #pragma unroll
            for (int j = 0; j < 8; ++j) part_s[wu][te_l + j] = pj[j];
        }
    }
    __syncthreads();

    // exp + slice sum (no max-sub: |e_raw| <= sum|v_a| < 26, exp can't overflow)
    float ex = 0.0f;
    if (tid < TE_SL) {
        float s = part_s[0][tid] + part_s[1][tid] + part_s[2][tid] +
                  part_s[3][tid] + part_s[4][tid] + part_s[5][tid] +
                  part_s[6][tid] + part_s[7][tid];
        ex = __expf(s);
        g_exs[wrE][b * TENC + te0 + tid] = ex;
    }
    float sw = ex;
    #pragma unroll
    for (int m = 16; m >= 1; m >>= 1)
        sw += __shfl_xor_sync(0xffffffffu, sw, m);
    if (lane == 0) red_s[wu] = sw;
    __syncthreads();
    if (tid == 0) {
        float tot = 0.0f;
        #pragma unroll
        for (int w = 0; w < 8; ++w) tot += red_s[w];
        g_psum[wrE][b * SLICES + slice] = tot;
    }
}

// ---- finalize e(511) ------------------------------------------------------
__global__ void kE(float* __restrict__ out) {
    const int bx = blockIdx.x;
    const int b = bx >> 3;
    const int slice = bx & 7;
    const int tid = threadIdx.x;
    float* e_out = out + (size_t)BQ * TDEC * EDIM;
    const float* ps = &g_psum[1][b * SLICES];       // 511 & 1 == 1
    float s = 0.0f;
    #pragma unroll
    for (int i = 0; i < SLICES; ++i) s += ps[i];
    float inv = 1.0f / s;
    int te = slice * TE_SL + tid;
    e_out[((size_t)b * TDEC + 511) * TENC + te] = g_exs[1][b * TENC + te] * inv;
}

// ---- final context GEMM: c[b,d,:] = sum_te e[b,d,te] * enc[b,te,:] --------
__global__ void __launch_bounds__(512)
kC(const float* __restrict__ enc, float* __restrict__ out) {
    const int dtile = blockIdx.x;     // 16 tiles of 32 d-rows
    const int b = blockIdx.y;
    const int tid = threadIdx.x;
    const int upair = tid & 255;
    const int dhalf = tid >> 8;       // 0..1 -> 16 d-rows each

    const ull* enc2 = reinterpret_cast<const ull*>(enc);
    const float* e_out = out + (size_t)BQ * TDEC * EDIM;

    __shared__ float es[32][128];
    ull acc[16];
    #pragma unroll
    for (int j = 0; j < 16; ++j) acc[j] = 0ull;

    for (int c = 0; c < 8; ++c) {     // te chunks of 128
        __syncthreads();
        for (int q = tid; q < 1024; q += 512) {   // 32 rows x 32 float4
            int row = q >> 5, col4 = q & 31;
            float4 v = __ldg((const float4*)
                &e_out[((size_t)b * TDEC + dtile * 32 + row) * TENC + c * 128 + col4 * 4]);
            *(float4*)&es[row][col4 * 4] = v;
        }
        __syncthreads();

        for (int te = 0; te < 128; te += 4) {
            ull ev0 = __ldg(&enc2[((size_t)b * TENC + c * 128 + te + 0) * NUP + upair]);
            ull ev1 = __ldg(&enc2[((size_t)b * TENC + c * 128 + te + 1) * NUP + upair]);
            ull ev2 = __ldg(&enc2[((size_t)b * TENC + c * 128 + te + 2) * NUP + upair]);
            ull ev3 = __ldg(&enc2[((size_t)b * TENC + c * 128 + te + 3) * NUP + upair]);
            #pragma unroll
            for (int j = 0; j < 16; ++j) {
                float4 e4 = *(const float4*)&es[dhalf * 16 + j][te];
                acc[j] = fma2(pack2(e4.x, e4.x), ev0, acc[j]);
                acc[j] = fma2(pack2(e4.y, e4.y), ev1, acc[j]);
                acc[j] = fma2(pack2(e4.z, e4.z), ev2, acc[j]);
                acc[j] = fma2(pack2(e4.w, e4.w), ev3, acc[j]);
            }
        }
    }

    #pragma unroll
    for (int j = 0; j < 16; ++j) {
        int d = dtile * 32 + dhalf * 16 + j;
        *(ull*)&out[((size_t)b * TDEC + d) * EDIM + 2 * upair] = acc[j];
    }
}

extern "C" void kernel_launch(void* const* d_in, const int* in_sizes, int n_in,
                              void* d_out, int out_size) {
    (void)in_sizes; (void)n_in; (void)out_size;
    const float* enc = (const float*)d_in[0];
    const float* dec = (const float*)d_in[1];
    const float* cw  = (const float*)d_in[2];
    const float* cb  = (const float*)d_in[3];
    const float* wl  = (const float*)d_in[4];
    const float* va  = (const float*)d_in[5];
    const float* ba  = (const float*)d_in[6];
    float* out = (float*)d_out;

    k_weff<<<32, 256>>>(cw, cb, wl);
    for (int t = 0; t < TDEC; ++t)
        kA<<<BQ * SLICES, 256>>>(t, enc, dec, va, ba, out);
    kE<<<BQ * SLICES, TE_SL>>>(out);
    dim3 gc(16, BQ);
    kC<<<gc, 512>>>(enc, out);
}

// round 12
// speedup vs baseline: 1.0959x; 1.0959x over previous
#include <cuda_runtime.h>
#include <cstdint>

// ---------------------------------------------------------------------------
// LocationSensitiveAttention — single persistent cluster kernel.
// B=32, T_ENC=1024, T_DEC=512, E=U=512, FILTERS=32, KERNEL=31.
//
// Launches: k_weff (fold conv_w@w_loc), kA_persist (ALL 512 decode steps),
// kC (c = e_out @ enc).
//
// kA_persist: grid 128, block 512, cluster (4,1,1). Each cluster = one batch;
// CTA rank r owns te-slice [r*256, r*256+256). All per-step cross-CTA
// communication (softmax sum, prev halo) is intra-cluster via DSMEM +
// barrier.cluster — clusters are the HW co-residency unit, and there is NO
// cross-cluster dependency, so this cannot deadlock regardless of scheduling.
// prev/exs live in shared memory for the whole scan (no global round-trips,
// no per-step kernel-launch overhead, L2 stays warm).
// ---------------------------------------------------------------------------

#define BQ 32
#define TENC 1024
#define TDEC 512
#define EDIM 512
#define NFILT 32
#define KW 31
#define NUP 256              // u-pairs (EDIM/2)

typedef unsigned long long ull;

// static device scratch (no allocation)
__device__ ull g_W2[KW * NUP];   // Weff packed f32x2 [k][upair]
__device__ ull g_cb2[NUP];       // conv_b @ w_loc packed

// ---- f32x2 helpers --------------------------------------------------------
__device__ __forceinline__ ull fma2(ull a, ull b, ull c) {
    ull d;
    asm("fma.rn.f32x2 %0, %1, %2, %3;" : "=l"(d) : "l"(a), "l"(b), "l"(c));
    return d;
}
__device__ __forceinline__ ull add2(ull a, ull b) {
    ull d;
    asm("add.rn.f32x2 %0, %1, %2;" : "=l"(d) : "l"(a), "l"(b));
    return d;
}
__device__ __forceinline__ ull pack2(float lo, float hi) {
    ull d;
    asm("mov.b64 %0, {%1, %2};" : "=l"(d) : "f"(lo), "f"(hi));
    return d;
}
__device__ __forceinline__ void unpack2(ull v, float& lo, float& hi) {
    asm("mov.b64 {%0, %1}, %2;" : "=f"(lo), "=f"(hi) : "l"(v));
}
// tanh(x) = 1 - 2/(1+exp(2x)); ex2+rcp approx (~1e-6), saturates correctly.
__device__ __forceinline__ float fast_tanh(float x) {
    float m = x * 2.8853900817779268f;    // 2*log2(e)
    float t, r;
    asm("ex2.approx.f32 %0, %1;" : "=f"(t) : "f"(m));
    float d = 1.0f + t;
    asm("rcp.approx.f32 %0, %1;" : "=f"(r) : "f"(d));
    return fmaf(-2.0f, r, 1.0f);
}
// ---- cluster helpers ------------------------------------------------------
__device__ __forceinline__ uint32_t smem_u32(const void* p) {
    uint32_t a;
    asm("{ .reg .u64 t; cvta.to.shared.u64 t, %1; cvt.u32.u64 %0, t; }"
        : "=r"(a) : "l"(p));
    return a;
}
__device__ __forceinline__ float dsmem_ldf(uint32_t laddr, int rank) {
    uint32_t ra;
    asm("mapa.shared::cluster.u32 %0, %1, %2;" : "=r"(ra) : "r"(laddr), "r"(rank));
    float v;
    asm volatile("ld.shared::cluster.f32 %0, [%1];" : "=f"(v) : "r"(ra));
    return v;
}
__device__ __forceinline__ void cluster_sync_all() {
    asm volatile("barrier.cluster.arrive.aligned;" ::: "memory");
    asm volatile("barrier.cluster.wait.aligned;" ::: "memory");
}

// ---- weight folding -------------------------------------------------------
__global__ void k_weff(const float* __restrict__ cw, const float* __restrict__ cb,
                       const float* __restrict__ wl) {
    int idx = blockIdx.x * blockDim.x + threadIdx.x;
    if (idx < KW * NUP) {
        int k = idx / NUP, up = idx % NUP;
        float slo = 0.0f, shi = 0.0f;
        #pragma unroll
        for (int f = 0; f < NFILT; ++f) {
            float w = cw[k * NFILT + f];
            slo += w * wl[f * EDIM + 2 * up];
            shi += w * wl[f * EDIM + 2 * up + 1];
        }
        g_W2[idx] = pack2(slo, shi);
    }
    if (idx < NUP) {
        float slo = 0.0f, shi = 0.0f;
        #pragma unroll
        for (int f = 0; f < NFILT; ++f) {
            float w = cb[f];
            slo += w * wl[f * EDIM + 2 * idx];
            shi += w * wl[f * EDIM + 2 * idx + 1];
        }
        g_cb2[idx] = pack2(slo, shi);
    }
}

// ---- the whole scan in one kernel ----------------------------------------
__global__ void __launch_bounds__(512, 1) __cluster_dims__(4, 1, 1)
kA_persist(const float* __restrict__ enc, const float* __restrict__ dec,
           const float* __restrict__ va, const float* __restrict__ ba,
           float* __restrict__ out) {
    const int bx = blockIdx.x;
    const int b = bx >> 2;
    const int rank = bx & 3;            // == cluster ctarank (1-D cluster of 4)
    const int te0 = rank * 256;

    const int tid = threadIdx.x;
    const int lane = tid & 31;
    const int warp = tid >> 5;
    const int wu = warp & 7;            // u-group
    const int half = warp >> 3;         // te half (0..1)
    const int upair = wu * 32 + lane;   // 0..255

    __shared__ ull   p2s[288];          // dup-packed prev(t-1) window
    __shared__ float prev_s[256];       // own cumulative alignments
    __shared__ float part_s[8][256];    // cross-warp partials
    __shared__ float exs_s[256];
    __shared__ float red_s[16];
    __shared__ float slice_sum;         // this CTA's exp-sum (DSMEM-read by peers)
    __shared__ float inv_s;

    const ull* enc2 = reinterpret_cast<const ull*>(enc);
    const ull* dec2 = reinterpret_cast<const ull*>(dec);
    const ull* va2  = reinterpret_cast<const ull*>(va);
    const ull* ba2  = reinterpret_cast<const ull*>(ba);
    float* e_out = out + (size_t)BQ * TDEC * EDIM;

    // init smem state (prev(−1) = 0)
    if (tid < 288) p2s[tid] = 0ull;
    if (tid < 256) prev_s[tid] = 0.0f;

    // per-thread constants
    float va_lo, va_hi;
    unpack2(__ldg(va2 + upair), va_lo, va_hi);
    const ull bias2 = add2(__ldg(ba2 + upair), g_cb2[upair]);
    const ull* enc_row = enc2 + ((size_t)b * TENC + te0) * NUP + upair;
    const ull* dec_row = dec2 + (size_t)b * TDEC * NUP + upair;
    const uint32_t prev_addr = smem_u32(prev_s);
    const uint32_t ssum_addr = smem_u32(&slice_sum);
    __syncthreads();

    for (int t = 0; t < TDEC; ++t) {
        const ull qb2 = add2(__ldg(dec_row + (size_t)t * NUP), bias2);

        // ---- loc (Toeplitz, f32x2) + tanh + v_a reduce: 16 tiles of 8 te --
        #pragma unroll 1
        for (int tile = 0; tile < 16; ++tile) {
            const int te_l = half * 128 + tile * 8;

            // enc loads hoisted above the FFMA2 chain (latency covered)
            ull ev[8];
            #pragma unroll
            for (int j = 0; j < 8; ++j)
                ev[j] = __ldg(enc_row + (size_t)(te_l + j) * NUP);

            ull r[8], acc[8];
            #pragma unroll
            for (int j = 0; j < 8; ++j) { r[j] = p2s[te_l + j]; acc[j] = 0ull; }
            #pragma unroll
            for (int k = 0; k < KW; ++k) {
                ull wk = __ldg(&g_W2[k * NUP + upair]);
                #pragma unroll
                for (int j = 0; j < 8; ++j)
                    acc[j] = fma2(r[(k + j) & 7], wk, acc[j]);
                if (k < KW - 1) r[k & 7] = p2s[te_l + k + 8];
            }

            float pj[8];
            #pragma unroll
            for (int j = 0; j < 8; ++j) {
                ull arg = add2(add2(acc[j], ev[j]), qb2);
                float xlo, xhi;
                unpack2(arg, xlo, xhi);
                pj[j] = fmaf(va_hi, fast_tanh(xhi), va_lo * fast_tanh(xlo));
            }
            #pragma unroll
            for (int j = 0; j < 8; ++j) {
                #pragma unroll
                for (int m = 16; m >= 1; m >>= 1)
                    pj[j] += __shfl_xor_sync(0xffffffffu, pj[j], m);
            }
            if (lane == 0) {
                #pragma unroll
                for (int j = 0; j < 8; ++j) part_s[wu][te_l + j] = pj[j];
            }
        }
        __syncthreads();

        // ---- exp + slice sum (no max-sub: |e_raw| <= sum|v_a| < 26) -------
        float ex = 0.0f;
        if (tid < 256) {
            float s = part_s[0][tid] + part_s[1][tid] + part_s[2][tid] +
                      part_s[3][tid] + part_s[4][tid] + part_s[5][tid] +
                      part_s[6][tid] + part_s[7][tid];
            ex = __expf(s);
            exs_s[tid] = ex;
        }
        float sw = ex;
        #pragma unroll
        for (int m = 16; m >= 1; m >>= 1)
            sw += __shfl_xor_sync(0xffffffffu, sw, m);
        if (lane == 0) red_s[warp] = sw;
        __syncthreads();
        if (tid == 0) {
            float tot = 0.0f;
            #pragma unroll
            for (int w = 0; w < 16; ++w) tot += red_s[w];
            slice_sum = tot;
        }

        // ---- cluster exchange of the 4 slice sums -------------------------
        cluster_sync_all();                    // slice_sum visible cluster-wide
        if (tid == 0) {
            float s0 = dsmem_ldf(ssum_addr, 0);
            float s1 = dsmem_ldf(ssum_addr, 1);
            float s2 = dsmem_ldf(ssum_addr, 2);
            float s3 = dsmem_ldf(ssum_addr, 3);
            inv_s = 1.0f / (s0 + s1 + s2 + s3);
        }
        __syncthreads();

        // ---- e, prev update, e_out output ---------------------------------
        if (tid < 256) {
            float e = exs_s[tid] * inv_s;
            __stcs(&e_out[((size_t)b * TDEC + t) * TENC + te0 + tid], e);
            prev_s[tid] += e;
        }

        // ---- rebuild window for next step (halo via DSMEM) ----------------
        cluster_sync_all();                    // all ranks' prev_s updated
        if (tid < 286) {
            int te_g = te0 - 15 + tid;
            float v = 0.0f;
            if (te_g >= 0 && te_g < TENC) {
                int r = te_g >> 8, off = te_g & 255;
                v = (r == rank) ? prev_s[off]
                                : dsmem_ldf(prev_addr + off * 4, r);
            }
            p2s[tid] = pack2(v, v);
        }
        __syncthreads();
    }
}

// ---- final context GEMM: c[b,d,:] = sum_te e[b,d,te] * enc[b,te,:] --------
__global__ void __launch_bounds__(512)
kC(const float* __restrict__ enc, float* __restrict__ out) {
    const int dtile = blockIdx.x;     // 16 tiles of 32 d-rows
    const int b = blockIdx.y;
    const int tid = threadIdx.x;
    const int upair = tid & 255;
    const int dhalf = tid >> 8;       // 0..1 -> 16 d-rows each

    const ull* enc2 = reinterpret_cast<const ull*>(enc);
    const float* e_out = out + (size_t)BQ * TDEC * EDIM;

    __shared__ float es[32][128];
    ull acc[16];
    #pragma unroll
    for (int j = 0; j < 16; ++j) acc[j] = 0ull;

    for (int c = 0; c < 8; ++c) {     // te chunks of 128
        __syncthreads();
        for (int q = tid; q < 1024; q += 512) {   // 32 rows x 32 float4
            int row = q >> 5, col4 = q & 31;
            float4 v = __ldg((const float4*)
                &e_out[((size_t)b * TDEC + dtile * 32 + row) * TENC + c * 128 + col4 * 4]);
            *(float4*)&es[row][col4 * 4] = v;
        }
        __syncthreads();

        for (int te = 0; te < 128; te += 4) {
            ull ev0 = __ldg(&enc2[((size_t)b * TENC + c * 128 + te + 0) * NUP + upair]);
            ull ev1 = __ldg(&enc2[((size_t)b * TENC + c * 128 + te + 1) * NUP + upair]);
            ull ev2 = __ldg(&enc2[((size_t)b * TENC + c * 128 + te + 2) * NUP + upair]);
            ull ev3 = __ldg(&enc2[((size_t)b * TENC + c * 128 + te + 3) * NUP + upair]);
            #pragma unroll
            for (int j = 0; j < 16; ++j) {
                float4 e4 = *(const float4*)&es[dhalf * 16 + j][te];
                acc[j] = fma2(pack2(e4.x, e4.x), ev0, acc[j]);
                acc[j] = fma2(pack2(e4.y, e4.y), ev1, acc[j]);
                acc[j] = fma2(pack2(e4.z, e4.z), ev2, acc[j]);
                acc[j] = fma2(pack2(e4.w, e4.w), ev3, acc[j]);
            }
        }
    }

    #pragma unroll
    for (int j = 0; j < 16; ++j) {
        int d = dtile * 32 + dhalf * 16 + j;
        *(ull*)&out[((size_t)b * TDEC + d) * EDIM + 2 * upair] = acc[j];
    }
}

extern "C" void kernel_launch(void* const* d_in, const int* in_sizes, int n_in,
                              void* d_out, int out_size) {
    (void)in_sizes; (void)n_in; (void)out_size;
    const float* enc = (const float*)d_in[0];
    const float* dec = (const float*)d_in[1];
    const float* cw  = (const float*)d_in[2];
    const float* cb  = (const float*)d_in[3];
    const float* wl  = (const float*)d_in[4];
    const float* va  = (const float*)d_in[5];
    const float* ba  = (const float*)d_in[6];
    float* out = (float*)d_out;

    k_weff<<<32, 256>>>(cw, cb, wl);
    kA_persist<<<BQ * 4, 512>>>(enc, dec, va, ba, out);
    dim3 gc(16, BQ);
    kC<<<gc, 512>>>(enc, out);
}